// round 13
// baseline (speedup 1.0000x reference)
#include <cuda_runtime.h>
#include <cuda_fp16.h>
#include <cstdint>

#define B_ 4
#define C_ 256
#define N_ 4096

// ---------------- device scratch (all fp16) ----------------
__device__ __half g_qf[(size_t)B_*N_*C_];   // normalized x, [b][n][c]
__device__ __half g_xf[(size_t)B_*N_*C_];   // raw x transposed, [b][n][c]
__device__ __half g_wf[C_*C_];              // W, [o][c]
__device__ __half g_v [(size_t)B_*C_*N_];   // conv out, [b][c][m]
__device__ __half g_p [(size_t)B_*N_*N_];   // P = relu(sim)^2, [b][i][j]

// ---------------- helpers ----------------
__device__ __forceinline__ uint32_t smem_u32(const void* p) {
    uint32_t a;
    asm("{ .reg .u64 t; cvta.to.shared.u64 t, %1; cvt.u32.u64 %0, t; }" : "=r"(a) : "l"(p));
    return a;
}

#define CP16(dst, src) \
    asm volatile("cp.async.cg.shared.global [%0], [%1], 16;" :: "r"(dst), "l"(src))
#define CPCOMMIT() asm volatile("cp.async.commit_group;" ::: "memory")
#define CPWAIT2()  asm volatile("cp.async.wait_group 2;" ::: "memory")
#define CPWAIT1()  asm volatile("cp.async.wait_group 1;" ::: "memory")
#define CPWAIT0()  asm volatile("cp.async.wait_group 0;" ::: "memory")

#define LDSM_X4(r, ad) \
    asm volatile("ldmatrix.sync.aligned.m8n8.x4.shared.b16 {%0,%1,%2,%3}, [%4];" \
        : "=r"((r)[0]), "=r"((r)[1]), "=r"((r)[2]), "=r"((r)[3]) : "r"(ad))
#define LDSM_X2(r, ad) \
    asm volatile("ldmatrix.sync.aligned.m8n8.x2.shared.b16 {%0,%1}, [%2];" \
        : "=r"((r)[0]), "=r"((r)[1]) : "r"(ad))
#define STSM_X4(ad, r0, r1, r2, r3) \
    asm volatile("stmatrix.sync.aligned.m8n8.x4.shared.b16 [%0], {%1,%2,%3,%4};" \
        :: "r"(ad), "r"(r0), "r"(r1), "r"(r2), "r"(r3))
#define STSM_X4_T(ad, r0, r1, r2, r3) \
    asm volatile("stmatrix.sync.aligned.m8n8.x4.trans.shared.b16 [%0], {%1,%2,%3,%4};" \
        :: "r"(ad), "r"(r0), "r"(r1), "r"(r2), "r"(r3))

#define MMAH(d, a, bb) \
    asm volatile("mma.sync.aligned.m16n8k16.row.col.f32.f16.f16.f32 " \
        "{%0,%1,%2,%3}, {%4,%5,%6,%7}, {%8,%9}, {%0,%1,%2,%3};" \
        : "+f"((d)[0]), "+f"((d)[1]), "+f"((d)[2]), "+f"((d)[3]) \
        : "r"((a)[0]), "r"((a)[1]), "r"((a)[2]), "r"((a)[3]), "r"((bb)[0]), "r"((bb)[1]))
#define MMAH16(d, a, bb) \
    asm volatile("mma.sync.aligned.m16n8k16.row.col.f16.f16.f16.f16 " \
        "{%0,%1}, {%2,%3,%4,%5}, {%6,%7}, {%0,%1};" \
        : "+r"((d)[0]), "+r"((d)[1]) \
        : "r"((a)[0]), "r"((a)[1]), "r"((a)[2]), "r"((a)[3]), "r"((bb)[0]), "r"((bb)[1]))

// swizzled 16B-chunk offset inside a [rows x 32 cols fp16] tile (64B rows)
__device__ __forceinline__ uint32_t swz(int row, int ch) {
    return (uint32_t)((row * 4 + (ch ^ ((row >> 1) & 3))) * 16);
}
// relu^2 on packed half2
__device__ __forceinline__ uint32_t relu2h2p(uint32_t p) {
    __half2 v = *(__half2*)&p;
    __half2 z = __floats2half2_rn(0.f, 0.f);
    v = __hmax2(v, z);
    v = __hmul2(v, v);
    return *(uint32_t*)&v;
}

// ---------------------------------------------------------------------------
// prep: per-pixel channel L2 norm -> fp16(raw x), fp16(normed x) in [b][n][c]
// ---------------------------------------------------------------------------
__global__ __launch_bounds__(256) void k_prep(const float* __restrict__ x) {
    __shared__ float tile[C_ * 33];
    __shared__ float red[8 * 32];
    __shared__ float rn[32];

    int b  = blockIdx.x >> 7;
    int n0 = (blockIdx.x & 127) * 32;
    int t  = threadIdx.x;
    int nl = t & 31;
    int cg = t >> 5;

    const float* xb = x + (size_t)b * C_ * N_;
#pragma unroll 8
    for (int p = 0; p < 32; ++p) {
        int c = cg + p * 8;
        tile[c * 33 + nl] = xb[(size_t)c * N_ + n0 + nl];
    }
    __syncthreads();

    float ss = 0.f;
#pragma unroll 8
    for (int c = cg; c < C_; c += 8) { float v = tile[c * 33 + nl]; ss += v * v; }
    red[cg * 32 + nl] = ss;
    __syncthreads();
    if (t < 32) {
        float s = 0.f;
#pragma unroll
        for (int g = 0; g < 8; ++g) s += red[g * 32 + t];
        rn[t] = 1.f / fmaxf(sqrtf(s), 1e-8f);
    }
    __syncthreads();

#pragma unroll 8
    for (int n = 0; n < 32; ++n) {
        size_t idx = (size_t)(b * N_ + n0 + n) * C_ + t;
        float xv = tile[t * 33 + n];
        g_xf[idx] = __float2half_rn(xv);
        g_qf[idx] = __float2half_rn(xv * rn[n]);
    }
}

__global__ __launch_bounds__(256) void k_prepW(const float* __restrict__ W) {
    int i = blockIdx.x * 256 + threadIdx.x;
    g_wf[i] = __float2half_rn(W[i]);
}

// ---------------------------------------------------------------------------
// k_conv: 128x128 GEMM, 2 CTA/SM, 3-stage, 64x32 warps, fp32 acc (unchanged).
// ---------------------------------------------------------------------------
__global__ void __launch_bounds__(256, 2) k_conv(const float* __restrict__ bias) {
    extern __shared__ __align__(128) char sm[];
    const uint32_t smb = smem_u32(sm);
    const int t = threadIdx.x;
    const int b = blockIdx.z;
    const int bx = blockIdx.x, by = blockIdx.y;
    constexpr int KCH = C_ / 32;

    const __half* af = g_xf + (size_t)b * N_ * C_ + (size_t)bx * 128 * C_;
    const __half* bf = g_wf + (size_t)by * 128 * C_;

    const int wid = t >> 5, lane = t & 31;
    const int wm = wid >> 2, wn = wid & 3;
    const int m0w = wm * 64, n0w = wn * 32;

    float acc[4][4][4];
#pragma unroll
    for (int i = 0; i < 4; ++i)
#pragma unroll
        for (int j = 0; j < 4; ++j)
#pragma unroll
            for (int r = 0; r < 4; ++r) acc[i][j][r] = 0.f;

#define PFC(kc_) do {                                                          \
        uint32_t st_ = smb + (uint32_t)((kc_) % 3) * 16384u;                   \
        int k0_ = (kc_) * 32;                                                  \
        _Pragma("unroll")                                                      \
        for (int i_ = 0; i_ < 2; ++i_) {                                       \
            int lin_ = t + i_ * 256;                                           \
            int row_ = lin_ >> 2, ch_ = lin_ & 3;                              \
            uint32_t so_ = swz(row_, ch_);                                     \
            CP16(st_ + so_,        af + (size_t)row_ * C_ + k0_ + ch_ * 8);    \
            CP16(st_ + 8192 + so_, bf + (size_t)row_ * C_ + k0_ + ch_ * 8);    \
        }                                                                      \
    } while (0)

    PFC(0); CPCOMMIT();
    PFC(1); CPCOMMIT();

    const int asub   = lane >> 3;
    const int arow   = (asub & 1) * 8 + (lane & 7);
    const int achoff = asub >> 1;
    const int bsub   = (lane >> 3) & 1;
    const int brow   = lane & 7;

#pragma unroll 1
    for (int kc = 0; kc < KCH; ++kc) {
        if (kc + 1 < KCH) CPWAIT1(); else CPWAIT0();
        __syncthreads();
        if (kc + 2 < KCH) { PFC(kc + 2); CPCOMMIT(); }

        uint32_t st = smb + (uint32_t)(kc % 3) * 16384u;
#pragma unroll
        for (int ks = 0; ks < 2; ++ks) {
            uint32_t Ah[4][4], Bh[4][2];
#pragma unroll
            for (int i = 0; i < 4; ++i)
                LDSM_X4(Ah[i], st + swz(m0w + i * 16 + arow, ks * 2 + achoff));
#pragma unroll
            for (int j = 0; j < 4; ++j)
                LDSM_X2(Bh[j], st + 8192 + swz(n0w + j * 8 + brow, ks * 2 + bsub));
#pragma unroll
            for (int i = 0; i < 4; ++i)
#pragma unroll
                for (int j = 0; j < 4; ++j)
                    MMAH(acc[i][j], Ah[i], Bh[j]);
        }
    }
#undef PFC

    float* Ds = (float*)sm;     // 64 * 129 * 4 = 33024 B
    const int jj = t & 127, seg = t >> 7;
    float bv = bias[by * 128 + jj];

#pragma unroll 1
    for (int h = 0; h < 2; ++h) {
        __syncthreads();
        if (wm == h) {
#pragma unroll
            for (int i = 0; i < 4; ++i) {
                int lr0 = i * 16 + (lane >> 2);
#pragma unroll
                for (int j = 0; j < 4; ++j) {
                    int c0 = n0w + j * 8 + (lane & 3) * 2;
                    Ds[lr0 * 129 + c0]           = acc[i][j][0];
                    Ds[lr0 * 129 + c0 + 1]       = acc[i][j][1];
                    Ds[(lr0 + 8) * 129 + c0]     = acc[i][j][2];
                    Ds[(lr0 + 8) * 129 + c0 + 1] = acc[i][j][3];
                }
            }
        }
        __syncthreads();

#pragma unroll 1
        for (int rb = 0; rb < 4; ++rb) {
            int lr0 = seg * 32 + rb * 8;
            __align__(16) __half hv[8];
#pragma unroll
            for (int u = 0; u < 8; ++u)
                hv[u] = __float2half_rn(Ds[(lr0 + u) * 129 + jj] + bv);
            size_t off = (size_t)b * C_ * N_ + (size_t)(by * 128 + jj) * N_
                       + bx * 128 + h * 64 + lr0;
            *(uint4*)(g_v + off) = *(uint4*)hv;
        }
    }
}

// ---------------------------------------------------------------------------
// k_sim: S[128n x 256m] = Q_bx[128,256] * Q_by[256,256]^T, fp16 accumulation,
// warp tile 64x64 (8 warps, 2x4), 3-stage 24KB, 2 CTA/SM.
// Triangular grid bx >= 2by (272 tiles/batch); mirror iff bx >= 2by+2.
// relu^2 in half2; dual stmatrix (normal + trans) staging, half passes.
// Diagonal P[n][n] overwritten to exactly 1.0.
// ---------------------------------------------------------------------------
__global__ void __launch_bounds__(256, 2) k_sim() {
    extern __shared__ __align__(128) char sm[];
    const uint32_t smb = smem_u32(sm);
    const int t = threadIdx.x;
    const int b = blockIdx.z;

    // id -> (by, bx): by in 0..15 (256-col blocks), bx in 2by..31 (128-row blocks)
    int rem = blockIdx.x, by = 0;
    while (rem >= 32 - 2 * by) { rem -= 32 - 2 * by; ++by; }
    const int bx = 2 * by + rem;

    const __half* af = g_qf + (size_t)b * N_ * C_ + (size_t)bx * 128 * C_;
    const __half* bf = g_qf + (size_t)b * N_ * C_ + (size_t)by * 256 * C_;
    constexpr int KCH = C_ / 32;   // 8

    const int wid = t >> 5, lane = t & 31;
    const int wm = wid >> 2, wn = wid & 3;        // 2 x 4
    const int m0w = wm * 64, n0w = wn * 64;

    uint32_t accH[4][8][2];
#pragma unroll
    for (int i = 0; i < 4; ++i)
#pragma unroll
        for (int j = 0; j < 8; ++j) { accH[i][j][0] = 0u; accH[i][j][1] = 0u; }

#define PFS(kc_) do {                                                          \
        uint32_t st_ = smb + (uint32_t)((kc_) % 3) * 24576u;                   \
        int k0_ = (kc_) * 32;                                                  \
        _Pragma("unroll")                                                      \
        for (int i_ = 0; i_ < 2; ++i_) {  /* A: 128 rows */                    \
            int lin_ = t + i_ * 256;                                           \
            int row_ = lin_ >> 2, ch_ = lin_ & 3;                              \
            CP16(st_ + swz(row_, ch_), af + (size_t)row_ * C_ + k0_ + ch_ * 8);\
        }                                                                      \
        _Pragma("unroll")                                                      \
        for (int i_ = 0; i_ < 4; ++i_) {  /* B: 256 rows */                    \
            int lin_ = t + i_ * 256;                                           \
            int row_ = lin_ >> 2, ch_ = lin_ & 3;                              \
            CP16(st_ + 8192 + swz(row_, ch_),                                  \
                 bf + (size_t)row_ * C_ + k0_ + ch_ * 8);                      \
        }                                                                      \
    } while (0)

    PFS(0); CPCOMMIT();
    PFS(1); CPCOMMIT();

    const int asub   = lane >> 3;
    const int arow   = (asub & 1) * 8 + (lane & 7);
    const int achoff = asub >> 1;
    const int bg     = lane >> 3;
    const int brow4  = (bg >> 1) * 8 + (lane & 7);
    const int bch    = bg & 1;

#pragma unroll 1
    for (int kc = 0; kc < KCH; ++kc) {
        if (kc + 1 < KCH) CPWAIT1(); else CPWAIT0();
        __syncthreads();
        if (kc + 2 < KCH) { PFS(kc + 2); CPCOMMIT(); }

        uint32_t st = smb + (uint32_t)(kc % 3) * 24576u;
#pragma unroll
        for (int ks = 0; ks < 2; ++ks) {
            uint32_t Ah[4][4], Bh[8][2];
#pragma unroll
            for (int i = 0; i < 4; ++i)
                LDSM_X4(Ah[i], st + swz(m0w + i * 16 + arow, ks * 2 + achoff));
#pragma unroll
            for (int jp = 0; jp < 4; ++jp)
                LDSM_X4((&Bh[2 * jp][0]),
                        st + 8192 + swz(n0w + jp * 16 + brow4, ks * 2 + bch));
#pragma unroll
            for (int i = 0; i < 4; ++i)
#pragma unroll
                for (int j = 0; j < 8; ++j)
                    MMAH16(accH[i][j], Ah[i], Bh[j]);
        }
    }
#undef PFS

    // ---- epilogue: relu^2 (half2), dual stmatrix staging, two half-passes ----
    // Ph[64][264] fp16 = 33792 B ; Pt[256][72] fp16 = 36864 B ; total 70656 <= 73728
    __half* Ph = (__half*)sm;
    __half* Pt = (__half*)(sm + 33792);
    const uint32_t ptb = smb + 33792;
    const int g  = lane >> 3;
    const int lr = lane & 7;
    const bool do_mirror = (bx >= 2 * by + 2);

#pragma unroll 1
    for (int h = 0; h < 2; ++h) {
        __syncthreads();          // stages dead (h=0) / previous half consumed
        if (wm == h) {
#pragma unroll
            for (int i = 0; i < 4; ++i) {
#pragma unroll
                for (int jp = 0; jp < 4; ++jp) {
                    uint32_t d0 = relu2h2p(accH[i][2*jp][0]);
                    uint32_t d1 = relu2h2p(accH[i][2*jp][1]);
                    uint32_t d2 = relu2h2p(accH[i][2*jp+1][0]);
                    uint32_t d3 = relu2h2p(accH[i][2*jp+1][1]);
                    int row = i * 16 + (g & 1) * 8 + lr;          // 0..63 local
                    int col = n0w + jp * 16 + (g >> 1) * 8;       // 0..255
                    STSM_X4(smb + (uint32_t)(row * 264 + col) * 2u, d0, d1, d2, d3);
                    int rowt = n0w + jp * 16 + (g >> 1) * 8 + lr; // 0..255
                    int colt = i * 16 + (g & 1) * 8;              // 0..63
                    STSM_X4_T(ptb + (uint32_t)(rowt * 72 + colt) * 2u, d0, d1, d2, d3);
                }
            }
        }
        __syncthreads();

        // direct (coalesced): P[bx*128 + h*64 + r][by*256 + 0..255]
        // each thread: one 64-half span = 8 x uint4
        {
            const int r = t >> 2, q = t & 3;
            const uint4* src = (const uint4*)(Ph + r * 264 + q * 64);
            uint4* dst = (uint4*)(g_p + (size_t)b * N_ * N_
                                  + (size_t)(bx * 128 + h * 64 + r) * N_
                                  + by * 256 + q * 64);
#pragma unroll
            for (int u = 0; u < 8; ++u) dst[u] = src[u];
        }

        // mirror (coalesced): P[by*256 + rt][bx*128 + h*64 + 0..63]
        // each thread: one full 64-half row = 8 x uint4
        if (do_mirror) {
            const uint4* src = (const uint4*)(Pt + t * 72);
            uint4* dst = (uint4*)(g_p + (size_t)b * N_ * N_
                                  + (size_t)(by * 256 + t) * N_
                                  + bx * 128 + h * 64);
#pragma unroll
            for (int u = 0; u < 8; ++u) dst[u] = src[u];
        }
    }

    // diagonal fix: tiles crossing the diagonal set P[n][n] = 1.0 exactly
    if ((bx >> 1) == by && t < 128) {
        size_t n = (size_t)bx * 128 + t;
        g_p[(size_t)b * N_ * N_ + n * N_ + n] = __float2half_rn(1.0f);
    }
}

// ---------------------------------------------------------------------------
// k2: out GEMM. D[128n x 128c] = P[128,4096] * V[128c,4096]^T, fp32 out.
// 2 CTA/SM, 64x32 warp tiles, 4-stage cp.async (unchanged R10).
// ---------------------------------------------------------------------------
__global__ void __launch_bounds__(256, 2) k2(float* __restrict__ outf) {
    extern __shared__ __align__(128) char sm[];
    const uint32_t smb = smem_u32(sm);
    const int t = threadIdx.x;
    const int b = blockIdx.z;
    const int bx = blockIdx.x, by = blockIdx.y;

    constexpr int KCH = N_ / 32;           // 128
    const __half* af = g_p + (size_t)b * N_ * N_ + (size_t)bx * 128 * N_;
    const __half* bf = g_v + (size_t)b * C_ * N_ + (size_t)by * 128 * N_;

    const int wid = t >> 5, lane = t & 31;
    const int wm = wid >> 2, wn = wid & 3;
    const int m0w = wm * 64, n0w = wn * 32;

    float acc[4][4][4];
#pragma unroll
    for (int i = 0; i < 4; ++i)
#pragma unroll
        for (int j = 0; j < 4; ++j)
#pragma unroll
            for (int r = 0; r < 4; ++r) acc[i][j][r] = 0.f;

#define PF2(kc_) do {                                                          \
        uint32_t st_ = smb + (uint32_t)((kc_) & 3) * 16384u;                   \
        int k0_ = (kc_) * 32;                                                  \
        _Pragma("unroll")                                                      \
        for (int i_ = 0; i_ < 2; ++i_) {                                       \
            int lin_ = t + i_ * 256;                                           \
            int row_ = lin_ >> 2, ch_ = lin_ & 3;                              \
            uint32_t so_ = swz(row_, ch_);                                     \
            CP16(st_ + so_,        af + (size_t)row_ * N_ + k0_ + ch_ * 8);    \
            CP16(st_ + 8192 + so_, bf + (size_t)row_ * N_ + k0_ + ch_ * 8);    \
        }                                                                      \
    } while (0)

    PF2(0); CPCOMMIT();
    PF2(1); CPCOMMIT();
    PF2(2); CPCOMMIT();

    const int asub   = lane >> 3;
    const int arow   = (asub & 1) * 8 + (lane & 7);
    const int achoff = asub >> 1;
    const int bsub   = (lane >> 3) & 1;
    const int brow   = lane & 7;

#pragma unroll 1
    for (int kc = 0; kc < KCH; ++kc) {
        if (kc + 3 < KCH) CPWAIT2(); else CPWAIT0();
        __syncthreads();
        if (kc + 3 < KCH) { PF2(kc + 3); CPCOMMIT(); }

        uint32_t st = smb + (uint32_t)(kc & 3) * 16384u;
#pragma unroll
        for (int ks = 0; ks < 2; ++ks) {
            uint32_t Ah[4][4], Bh[4][2];
#pragma unroll
            for (int i = 0; i < 4; ++i)
                LDSM_X4(Ah[i], st + swz(m0w + i * 16 + arow, ks * 2 + achoff));
#pragma unroll
            for (int j = 0; j < 4; ++j)
                LDSM_X2(Bh[j], st + 8192 + swz(n0w + j * 8 + brow, ks * 2 + bsub));
#pragma unroll
            for (int i = 0; i < 4; ++i)
#pragma unroll
                for (int j = 0; j < 4; ++j)
                    MMAH(acc[i][j], Ah[i], Bh[j]);
        }
    }
#undef PF2

    float* Ds = (float*)sm;     // 64 * 129 * 4 = 33024 B
    const int jj = t & 127, seg = t >> 7;

#pragma unroll 1
    for (int h = 0; h < 2; ++h) {
        __syncthreads();
        if (wm == h) {
#pragma unroll
            for (int i = 0; i < 4; ++i) {
                int lr0 = i * 16 + (lane >> 2);
#pragma unroll
                for (int j = 0; j < 4; ++j) {
                    int c0 = n0w + j * 8 + (lane & 3) * 2;
                    Ds[lr0 * 129 + c0]           = acc[i][j][0];
                    Ds[lr0 * 129 + c0 + 1]       = acc[i][j][1];
                    Ds[(lr0 + 8) * 129 + c0]     = acc[i][j][2];
                    Ds[(lr0 + 8) * 129 + c0 + 1] = acc[i][j][3];
                }
            }
        }
        __syncthreads();

#pragma unroll 1
        for (int rb = 0; rb < 4; ++rb) {
            int lr0 = seg * 32 + rb * 8;
            float* orow = outf + (size_t)b * C_ * N_ + (size_t)(by * 128 + jj) * N_
                        + bx * 128 + h * 64 + lr0;
            float4 v0, v1;
            v0.x = Ds[(lr0 + 0) * 129 + jj];
            v0.y = Ds[(lr0 + 1) * 129 + jj];
            v0.z = Ds[(lr0 + 2) * 129 + jj];
            v0.w = Ds[(lr0 + 3) * 129 + jj];
            v1.x = Ds[(lr0 + 4) * 129 + jj];
            v1.y = Ds[(lr0 + 5) * 129 + jj];
            v1.z = Ds[(lr0 + 6) * 129 + jj];
            v1.w = Ds[(lr0 + 7) * 129 + jj];
            *(float4*)(orow)     = v0;
            *(float4*)(orow + 4) = v1;
        }
    }
}

// ---------------------------------------------------------------------------
extern "C" void kernel_launch(void* const* d_in, const int* in_sizes, int n_in,
                              void* d_out, int out_size) {
    const float* x    = (const float*)d_in[0];
    const float* Wm   = (const float*)d_in[1];
    const float* bias = (const float*)d_in[2];
    float* out = (float*)d_out;

    const int SMEM_C  = 3 * 16384;   // 48KB
    const int SMEM_S  = 3 * 24576;   // 72KB (>= 70656 epilogue staging)
    const int SMEM_K2 = 4 * 16384;   // 64KB
    cudaFuncSetAttribute(k_conv, cudaFuncAttributeMaxDynamicSharedMemorySize, SMEM_C);
    cudaFuncSetAttribute(k_sim,  cudaFuncAttributeMaxDynamicSharedMemorySize, SMEM_S);
    cudaFuncSetAttribute(k2,     cudaFuncAttributeMaxDynamicSharedMemorySize, SMEM_K2);

    k_prep<<<B_ * (N_ / 32), 256>>>(x);
    k_prepW<<<C_ * C_ / 256, 256>>>(Wm);

    k_conv<<<dim3(N_ / 128, C_ / 128, B_), 256, SMEM_C>>>(bias);

    int tiles = 0;
    for (int by = 0; by < N_ / 256; ++by) tiles += (N_ / 128) - 2 * by;   // 272
    k_sim<<<dim3(tiles, 1, B_), 256, SMEM_S>>>();

    k2<<<dim3(N_ / 128, C_ / 128, B_), 256, SMEM_K2>>>(out);
}

// round 14
// speedup vs baseline: 1.0788x; 1.0788x over previous
#include <cuda_runtime.h>
#include <cuda_fp16.h>
#include <cstdint>

#define B_ 4
#define C_ 256
#define N_ 4096
#define TRI 528   // triangular 128x128 sim tiles per batch (bx<=by)

// ---------------- device scratch (all fp16) ----------------
__device__ __half g_qf[(size_t)B_*N_*C_];   // normalized x, [b][n][c]
__device__ __half g_xf[(size_t)B_*N_*C_];   // raw x transposed, [b][n][c]
__device__ __half g_wf[C_*C_];              // W, [o][c]
__device__ __half g_v [(size_t)B_*C_*N_];   // conv out, [b][c][m]
__device__ __half g_p [(size_t)B_*N_*N_];   // P = relu(sim)^2, [b][i][j]

// ---------------- helpers ----------------
__device__ __forceinline__ uint32_t smem_u32(const void* p) {
    uint32_t a;
    asm("{ .reg .u64 t; cvta.to.shared.u64 t, %1; cvt.u32.u64 %0, t; }" : "=r"(a) : "l"(p));
    return a;
}

#define CP16(dst, src) \
    asm volatile("cp.async.cg.shared.global [%0], [%1], 16;" :: "r"(dst), "l"(src))
#define CPCOMMIT() asm volatile("cp.async.commit_group;" ::: "memory")
#define CPWAIT2()  asm volatile("cp.async.wait_group 2;" ::: "memory")
#define CPWAIT1()  asm volatile("cp.async.wait_group 1;" ::: "memory")
#define CPWAIT0()  asm volatile("cp.async.wait_group 0;" ::: "memory")

#define LDSM_X4(r, ad) \
    asm volatile("ldmatrix.sync.aligned.m8n8.x4.shared.b16 {%0,%1,%2,%3}, [%4];" \
        : "=r"((r)[0]), "=r"((r)[1]), "=r"((r)[2]), "=r"((r)[3]) : "r"(ad))
#define LDSM_X2(r, ad) \
    asm volatile("ldmatrix.sync.aligned.m8n8.x2.shared.b16 {%0,%1}, [%2];" \
        : "=r"((r)[0]), "=r"((r)[1]) : "r"(ad))
#define STSM_X4(ad, r0, r1, r2, r3) \
    asm volatile("stmatrix.sync.aligned.m8n8.x4.shared.b16 [%0], {%1,%2,%3,%4};" \
        :: "r"(ad), "r"(r0), "r"(r1), "r"(r2), "r"(r3))
#define STSM_X4_T(ad, r0, r1, r2, r3) \
    asm volatile("stmatrix.sync.aligned.m8n8.x4.trans.shared.b16 [%0], {%1,%2,%3,%4};" \
        :: "r"(ad), "r"(r0), "r"(r1), "r"(r2), "r"(r3))

#define MMAH(d, a, bb) \
    asm volatile("mma.sync.aligned.m16n8k16.row.col.f32.f16.f16.f32 " \
        "{%0,%1,%2,%3}, {%4,%5,%6,%7}, {%8,%9}, {%0,%1,%2,%3};" \
        : "+f"((d)[0]), "+f"((d)[1]), "+f"((d)[2]), "+f"((d)[3]) \
        : "r"((a)[0]), "r"((a)[1]), "r"((a)[2]), "r"((a)[3]), "r"((bb)[0]), "r"((bb)[1]))

// swizzled 16B-chunk offset inside a [rows x 32 cols fp16] tile (64B rows)
__device__ __forceinline__ uint32_t swz(int row, int ch) {
    return (uint32_t)((row * 4 + (ch ^ ((row >> 1) & 3))) * 16);
}
__device__ __forceinline__ uint32_t relu2h2(float a, float b) {
    float xa = fmaxf(a, 0.f), xb = fmaxf(b, 0.f);
    __half2 h = __floats2half2_rn(xa * xa, xb * xb);
    return *(uint32_t*)&h;
}

// ---------------------------------------------------------------------------
// fused prep: blocks [0,512) = per-pixel L2 norm -> g_xf/g_qf;
//             blocks [512,576) = W -> g_wf fp16
// ---------------------------------------------------------------------------
__global__ __launch_bounds__(256) void k_prep(const float* __restrict__ x,
                                              const float* __restrict__ W) {
    if (blockIdx.x >= 512) {
        int i4 = (blockIdx.x - 512) * 1024 + threadIdx.x * 4;
        float4 w = *(const float4*)(W + i4);
        __align__(8) __half hv[4];
        hv[0] = __float2half_rn(w.x); hv[1] = __float2half_rn(w.y);
        hv[2] = __float2half_rn(w.z); hv[3] = __float2half_rn(w.w);
        *(uint2*)(g_wf + i4) = *(uint2*)hv;
        return;
    }

    __shared__ float tile[C_ * 33];
    __shared__ float red[8 * 32];
    __shared__ float rn[32];

    int b  = blockIdx.x >> 7;
    int n0 = (blockIdx.x & 127) * 32;
    int t  = threadIdx.x;
    int nl = t & 31;
    int cg = t >> 5;

    const float* xb = x + (size_t)b * C_ * N_;
#pragma unroll 8
    for (int p = 0; p < 32; ++p) {
        int c = cg + p * 8;
        tile[c * 33 + nl] = xb[(size_t)c * N_ + n0 + nl];
    }
    __syncthreads();

    float ss = 0.f;
#pragma unroll 8
    for (int c = cg; c < C_; c += 8) { float v = tile[c * 33 + nl]; ss += v * v; }
    red[cg * 32 + nl] = ss;
    __syncthreads();
    if (t < 32) {
        float s = 0.f;
#pragma unroll
        for (int g = 0; g < 8; ++g) s += red[g * 32 + t];
        rn[t] = 1.f / fmaxf(sqrtf(s), 1e-8f);
    }
    __syncthreads();

#pragma unroll 8
    for (int n = 0; n < 32; ++n) {
        size_t idx = (size_t)(b * N_ + n0 + n) * C_ + t;
        float xv = tile[t * 33 + n];
        g_xf[idx] = __float2half_rn(xv);
        g_qf[idx] = __float2half_rn(xv * rn[n]);
    }
}

// ---------------------------------------------------------------------------
// fused GEMM: blocks [0,TRI) = sim tile (triangular bx<=by, dual stmatrix
// epilogue + mirror); blocks [TRI,TRI+64) = conv tile (fp32 Ds epilogue).
// 128x128 tiles, 2 CTA/SM, 3-stage, 64x32 warp tiles (R10-proven mainloop).
// ---------------------------------------------------------------------------
__global__ void __launch_bounds__(256, 2) k_gemm(const float* __restrict__ bias) {
    extern __shared__ __align__(128) char sm[];
    const uint32_t smb = smem_u32(sm);
    const int t = threadIdx.x;
    const int b = blockIdx.z;

    const bool is_sim = (blockIdx.x < TRI);
    int bx, by;
    if (is_sim) {
        int id = blockIdx.x;
        int byy = (int)((sqrtf(8.f * id + 1.f) - 1.f) * 0.5f);
        while ((byy + 1) * (byy + 2) / 2 <= id) ++byy;
        while (byy * (byy + 1) / 2 > id) --byy;
        by = byy; bx = id - byy * (byy + 1) / 2;   // bx <= by
    } else {
        int id2 = blockIdx.x - TRI;
        bx = id2 & 31; by = id2 >> 5;              // conv: 32 x 2
    }

    constexpr int KCH = C_ / 32;

    const __half *af, *bf;
    if (is_sim) {
        af = g_qf + (size_t)b * N_ * C_ + (size_t)bx * 128 * C_;
        bf = g_qf + (size_t)b * N_ * C_ + (size_t)by * 128 * C_;
    } else {
        af = g_xf + (size_t)b * N_ * C_ + (size_t)bx * 128 * C_;
        bf = g_wf + (size_t)by * 128 * C_;
    }

    const int wid = t >> 5, lane = t & 31;
    const int wm = wid >> 2, wn = wid & 3;
    const int m0w = wm * 64, n0w = wn * 32;

    float acc[4][4][4];
#pragma unroll
    for (int i = 0; i < 4; ++i)
#pragma unroll
        for (int j = 0; j < 4; ++j)
#pragma unroll
            for (int r = 0; r < 4; ++r) acc[i][j][r] = 0.f;

#define PF1(kc_) do {                                                          \
        uint32_t st_ = smb + (uint32_t)((kc_) % 3) * 16384u;                   \
        int k0_ = (kc_) * 32;                                                  \
        _Pragma("unroll")                                                      \
        for (int i_ = 0; i_ < 2; ++i_) {                                       \
            int lin_ = t + i_ * 256;                                           \
            int row_ = lin_ >> 2, ch_ = lin_ & 3;                              \
            uint32_t so_ = swz(row_, ch_);                                     \
            CP16(st_ + so_,        af + (size_t)row_ * C_ + k0_ + ch_ * 8);    \
            CP16(st_ + 8192 + so_, bf + (size_t)row_ * C_ + k0_ + ch_ * 8);    \
        }                                                                      \
    } while (0)

    PF1(0); CPCOMMIT();
    PF1(1); CPCOMMIT();

    const int asub   = lane >> 3;
    const int arow   = (asub & 1) * 8 + (lane & 7);
    const int achoff = asub >> 1;
    const int bsub   = (lane >> 3) & 1;
    const int brow   = lane & 7;

#pragma unroll 1
    for (int kc = 0; kc < KCH; ++kc) {
        if (kc + 1 < KCH) CPWAIT1(); else CPWAIT0();
        __syncthreads();
        if (kc + 2 < KCH) { PF1(kc + 2); CPCOMMIT(); }

        uint32_t st = smb + (uint32_t)(kc % 3) * 16384u;
#pragma unroll
        for (int ks = 0; ks < 2; ++ks) {
            uint32_t Ah[4][4], Bh[4][2];
#pragma unroll
            for (int i = 0; i < 4; ++i)
                LDSM_X4(Ah[i], st + swz(m0w + i * 16 + arow, ks * 2 + achoff));
#pragma unroll
            for (int j = 0; j < 4; ++j)
                LDSM_X2(Bh[j], st + 8192 + swz(n0w + j * 8 + brow, ks * 2 + bsub));
#pragma unroll
            for (int i = 0; i < 4; ++i)
#pragma unroll
                for (int j = 0; j < 4; ++j)
                    MMAH(acc[i][j], Ah[i], Bh[j]);
        }
    }
#undef PF1

    if (is_sim) {
        // ---- sim epilogue (R10): dual stmatrix staging, two half-passes ----
        __half* Ph = (__half*)sm;                 // 64 x 136 = 17408 B
        __half* Pt = (__half*)(sm + 17408);       // 128 x 72 = 18432 B
        const uint32_t ptb = smb + 17408;
        const int g  = lane >> 3;
        const int lr = lane & 7;

#pragma unroll 1
        for (int h = 0; h < 2; ++h) {
            __syncthreads();
            if (wm == h) {
#pragma unroll
                for (int i = 0; i < 4; ++i) {
#pragma unroll
                    for (int jp = 0; jp < 2; ++jp) {
                        uint32_t d0 = relu2h2(acc[i][2*jp][0],   acc[i][2*jp][1]);
                        uint32_t d1 = relu2h2(acc[i][2*jp][2],   acc[i][2*jp][3]);
                        uint32_t d2 = relu2h2(acc[i][2*jp+1][0], acc[i][2*jp+1][1]);
                        uint32_t d3 = relu2h2(acc[i][2*jp+1][2], acc[i][2*jp+1][3]);
                        int row = i * 16 + (g & 1) * 8 + lr;
                        int col = n0w + jp * 16 + (g >> 1) * 8;
                        STSM_X4(smb + (uint32_t)(row * 136 + col) * 2u, d0, d1, d2, d3);
                        int rowt = n0w + jp * 16 + (g >> 1) * 8 + lr;
                        int colt = i * 16 + (g & 1) * 8;
                        STSM_X4_T(ptb + (uint32_t)(rowt * 72 + colt) * 2u, d0, d1, d2, d3);
                    }
                }
            }
            __syncthreads();

            // direct (coalesced): P[bx*128 + h*64 + r][by*128 + 0..127]
            {
                const int r = t >> 2, q = t & 3;
                const uint4* src = (const uint4*)(Ph + r * 136) + q * 4;
                uint4* dst = (uint4*)(g_p + (size_t)b * N_ * N_
                                      + (size_t)(bx * 128 + h * 64 + r) * N_
                                      + by * 128) + q * 4;
#pragma unroll
                for (int u = 0; u < 4; ++u) dst[u] = src[u];
            }

            // mirror (coalesced, bx != by): P[by*128 + rt][bx*128 + h*64 + 0..63]
            if (bx != by) {
                const int rt = t >> 1, hc = t & 1;
                const uint4* src = (const uint4*)(Pt + rt * 72) + hc * 4;
                uint4* dst = (uint4*)(g_p + (size_t)b * N_ * N_
                                      + (size_t)(by * 128 + rt) * N_
                                      + bx * 128 + h * 64) + hc * 4;
#pragma unroll
                for (int u = 0; u < 4; ++u) dst[u] = src[u];
            }
        }
    } else {
        // ---- conv epilogue (R10): fp32 Ds, two half-passes, fp16 store ----
        float* Ds = (float*)sm;     // 64 * 129 * 4 = 33024 B
        const int jj = t & 127, seg = t >> 7;
        float bv = bias[by * 128 + jj];

#pragma unroll 1
        for (int h = 0; h < 2; ++h) {
            __syncthreads();
            if (wm == h) {
#pragma unroll
                for (int i = 0; i < 4; ++i) {
                    int lr0 = i * 16 + (lane >> 2);
#pragma unroll
                    for (int j = 0; j < 4; ++j) {
                        int c0 = n0w + j * 8 + (lane & 3) * 2;
                        Ds[lr0 * 129 + c0]           = acc[i][j][0];
                        Ds[lr0 * 129 + c0 + 1]       = acc[i][j][1];
                        Ds[(lr0 + 8) * 129 + c0]     = acc[i][j][2];
                        Ds[(lr0 + 8) * 129 + c0 + 1] = acc[i][j][3];
                    }
                }
            }
            __syncthreads();

#pragma unroll 1
            for (int rb = 0; rb < 4; ++rb) {
                int lr0 = seg * 32 + rb * 8;
                __align__(16) __half hv[8];
#pragma unroll
                for (int u = 0; u < 8; ++u)
                    hv[u] = __float2half_rn(Ds[(lr0 + u) * 129 + jj] + bv);
                size_t off = (size_t)b * C_ * N_ + (size_t)(by * 128 + jj) * N_
                           + bx * 128 + h * 64 + lr0;
                *(uint4*)(g_v + off) = *(uint4*)hv;
            }
        }
    }
}

// ---------------------------------------------------------------------------
// k2: out GEMM. D[128n x 128c] = P[128,4096] * V[128c,4096]^T, fp32 out.
// 2 CTA/SM, 64x32 warp tiles, 4-stage cp.async (unchanged R10).
// ---------------------------------------------------------------------------
__global__ void __launch_bounds__(256, 2) k2(float* __restrict__ outf) {
    extern __shared__ __align__(128) char sm[];
    const uint32_t smb = smem_u32(sm);
    const int t = threadIdx.x;
    const int b = blockIdx.z;
    const int bx = blockIdx.x, by = blockIdx.y;

    constexpr int KCH = N_ / 32;           // 128
    const __half* af = g_p + (size_t)b * N_ * N_ + (size_t)bx * 128 * N_;
    const __half* bf = g_v + (size_t)b * C_ * N_ + (size_t)by * 128 * N_;

    const int wid = t >> 5, lane = t & 31;
    const int wm = wid >> 2, wn = wid & 3;
    const int m0w = wm * 64, n0w = wn * 32;

    float acc[4][4][4];
#pragma unroll
    for (int i = 0; i < 4; ++i)
#pragma unroll
        for (int j = 0; j < 4; ++j)
#pragma unroll
            for (int r = 0; r < 4; ++r) acc[i][j][r] = 0.f;

#define PF2(kc_) do {                                                          \
        uint32_t st_ = smb + (uint32_t)((kc_) & 3) * 16384u;                   \
        int k0_ = (kc_) * 32;                                                  \
        _Pragma("unroll")                                                      \
        for (int i_ = 0; i_ < 2; ++i_) {                                       \
            int lin_ = t + i_ * 256;                                           \
            int row_ = lin_ >> 2, ch_ = lin_ & 3;                              \
            uint32_t so_ = swz(row_, ch_);                                     \
            CP16(st_ + so_,        af + (size_t)row_ * N_ + k0_ + ch_ * 8);    \
            CP16(st_ + 8192 + so_, bf + (size_t)row_ * N_ + k0_ + ch_ * 8);    \
        }                                                                      \
    } while (0)

    PF2(0); CPCOMMIT();
    PF2(1); CPCOMMIT();
    PF2(2); CPCOMMIT();

    const int asub   = lane >> 3;
    const int arow   = (asub & 1) * 8 + (lane & 7);
    const int achoff = asub >> 1;
    const int bsub   = (lane >> 3) & 1;
    const int brow   = lane & 7;

#pragma unroll 1
    for (int kc = 0; kc < KCH; ++kc) {
        if (kc + 3 < KCH) CPWAIT2(); else CPWAIT0();
        __syncthreads();
        if (kc + 3 < KCH) { PF2(kc + 3); CPCOMMIT(); }

        uint32_t st = smb + (uint32_t)(kc & 3) * 16384u;
#pragma unroll
        for (int ks = 0; ks < 2; ++ks) {
            uint32_t Ah[4][4], Bh[4][2];
#pragma unroll
            for (int i = 0; i < 4; ++i)
                LDSM_X4(Ah[i], st + swz(m0w + i * 16 + arow, ks * 2 + achoff));
#pragma unroll
            for (int j = 0; j < 4; ++j)
                LDSM_X2(Bh[j], st + 8192 + swz(n0w + j * 8 + brow, ks * 2 + bsub));
#pragma unroll
            for (int i = 0; i < 4; ++i)
#pragma unroll
                for (int j = 0; j < 4; ++j)
                    MMAH(acc[i][j], Ah[i], Bh[j]);
        }
    }
#undef PF2

    float* Ds = (float*)sm;     // 64 * 129 * 4 = 33024 B
    const int jj = t & 127, seg = t >> 7;

#pragma unroll 1
    for (int h = 0; h < 2; ++h) {
        __syncthreads();
        if (wm == h) {
#pragma unroll
            for (int i = 0; i < 4; ++i) {
                int lr0 = i * 16 + (lane >> 2);
#pragma unroll
                for (int j = 0; j < 4; ++j) {
                    int c0 = n0w + j * 8 + (lane & 3) * 2;
                    Ds[lr0 * 129 + c0]           = acc[i][j][0];
                    Ds[lr0 * 129 + c0 + 1]       = acc[i][j][1];
                    Ds[(lr0 + 8) * 129 + c0]     = acc[i][j][2];
                    Ds[(lr0 + 8) * 129 + c0 + 1] = acc[i][j][3];
                }
            }
        }
        __syncthreads();

#pragma unroll 1
        for (int rb = 0; rb < 4; ++rb) {
            int lr0 = seg * 32 + rb * 8;
            float* orow = outf + (size_t)b * C_ * N_ + (size_t)(by * 128 + jj) * N_
                        + bx * 128 + h * 64 + lr0;
            float4 v0, v1;
            v0.x = Ds[(lr0 + 0) * 129 + jj];
            v0.y = Ds[(lr0 + 1) * 129 + jj];
            v0.z = Ds[(lr0 + 2) * 129 + jj];
            v0.w = Ds[(lr0 + 3) * 129 + jj];
            v1.x = Ds[(lr0 + 4) * 129 + jj];
            v1.y = Ds[(lr0 + 5) * 129 + jj];
            v1.z = Ds[(lr0 + 6) * 129 + jj];
            v1.w = Ds[(lr0 + 7) * 129 + jj];
            *(float4*)(orow)     = v0;
            *(float4*)(orow + 4) = v1;
        }
    }
}

// ---------------------------------------------------------------------------
extern "C" void kernel_launch(void* const* d_in, const int* in_sizes, int n_in,
                              void* d_out, int out_size) {
    const float* x    = (const float*)d_in[0];
    const float* Wm   = (const float*)d_in[1];
    const float* bias = (const float*)d_in[2];
    float* out = (float*)d_out;

    const int SMEM1 = 3 * 16384;   // 48KB, 2 CTA/SM (>= 35840 sim staging)
    const int SMEM2 = 4 * 16384;   // 64KB, 2 CTA/SM
    cudaFuncSetAttribute(k_gemm, cudaFuncAttributeMaxDynamicSharedMemorySize, SMEM1);
    cudaFuncSetAttribute(k2,     cudaFuncAttributeMaxDynamicSharedMemorySize, SMEM2);

    // fused prep: 512 norm blocks + 64 W-convert blocks
    k_prep<<<512 + 64, 256>>>(x, Wm);

    // fused GEMM: 528 sim tiles + 64 conv tiles, per batch
    k_gemm<<<dim3(TRI + 64, 1, B_), 256, SMEM1>>>(bias);

    k2<<<dim3(N_ / 128, C_ / 128, B_), 256, SMEM2>>>(out);
}

// round 15
// speedup vs baseline: 1.0884x; 1.0089x over previous
#include <cuda_runtime.h>
#include <cuda_fp16.h>
#include <cstdint>

#define B_ 4
#define C_ 256
#define N_ 4096
#define TRI 528   // triangular 128x128 sim tiles per batch (bx<=by)

// ---------------- device scratch (all fp16) ----------------
__device__ __half g_qf[(size_t)B_*N_*C_];   // normalized x, [b][n][c]
__device__ __half g_xf[(size_t)B_*N_*C_];   // raw x transposed, [b][n][c]
__device__ __half g_wf[C_*C_];              // W, [o][c]
__device__ __half g_v [(size_t)B_*C_*N_];   // conv out, [b][c][m]
__device__ __half g_p [(size_t)B_*N_*N_];   // P = relu(sim)^2, [b][i][j]

// ---------------- helpers ----------------
__device__ __forceinline__ uint32_t smem_u32(const void* p) {
    uint32_t a;
    asm("{ .reg .u64 t; cvta.to.shared.u64 t, %1; cvt.u32.u64 %0, t; }" : "=r"(a) : "l"(p));
    return a;
}

#define CP16(dst, src) \
    asm volatile("cp.async.cg.shared.global [%0], [%1], 16;" :: "r"(dst), "l"(src))
#define CPCOMMIT() asm volatile("cp.async.commit_group;" ::: "memory")
#define CPWAIT3()  asm volatile("cp.async.wait_group 3;" ::: "memory")
#define CPWAIT1()  asm volatile("cp.async.wait_group 1;" ::: "memory")
#define CPWAIT0()  asm volatile("cp.async.wait_group 0;" ::: "memory")

#define LDSM_X4(r, ad) \
    asm volatile("ldmatrix.sync.aligned.m8n8.x4.shared.b16 {%0,%1,%2,%3}, [%4];" \
        : "=r"((r)[0]), "=r"((r)[1]), "=r"((r)[2]), "=r"((r)[3]) : "r"(ad))
#define LDSM_X2(r, ad) \
    asm volatile("ldmatrix.sync.aligned.m8n8.x2.shared.b16 {%0,%1}, [%2];" \
        : "=r"((r)[0]), "=r"((r)[1]) : "r"(ad))
#define STSM_X4(ad, r0, r1, r2, r3) \
    asm volatile("stmatrix.sync.aligned.m8n8.x4.shared.b16 [%0], {%1,%2,%3,%4};" \
        :: "r"(ad), "r"(r0), "r"(r1), "r"(r2), "r"(r3))
#define STSM_X4_T(ad, r0, r1, r2, r3) \
    asm volatile("stmatrix.sync.aligned.m8n8.x4.trans.shared.b16 [%0], {%1,%2,%3,%4};" \
        :: "r"(ad), "r"(r0), "r"(r1), "r"(r2), "r"(r3))

#define MMAH(d, a, bb) \
    asm volatile("mma.sync.aligned.m16n8k16.row.col.f32.f16.f16.f32 " \
        "{%0,%1,%2,%3}, {%4,%5,%6,%7}, {%8,%9}, {%0,%1,%2,%3};" \
        : "+f"((d)[0]), "+f"((d)[1]), "+f"((d)[2]), "+f"((d)[3]) \
        : "r"((a)[0]), "r"((a)[1]), "r"((a)[2]), "r"((a)[3]), "r"((bb)[0]), "r"((bb)[1]))

// swizzled 16B-chunk offset inside a [rows x 32 cols fp16] tile (64B rows)
__device__ __forceinline__ uint32_t swz(int row, int ch) {
    return (uint32_t)((row * 4 + (ch ^ ((row >> 1) & 3))) * 16);
}
__device__ __forceinline__ uint32_t relu2h2(float a, float b) {
    float xa = fmaxf(a, 0.f), xb = fmaxf(b, 0.f);
    __half2 h = __floats2half2_rn(xa * xa, xb * xb);
    return *(uint32_t*)&h;
}

// ---------------------------------------------------------------------------
// fused prep: blocks [0,512) = per-pixel L2 norm -> g_xf/g_qf;
//             blocks [512,576) = W -> g_wf fp16
// ---------------------------------------------------------------------------
__global__ __launch_bounds__(256) void k_prep(const float* __restrict__ x,
                                              const float* __restrict__ W) {
    if (blockIdx.x >= 512) {
        int i4 = (blockIdx.x - 512) * 1024 + threadIdx.x * 4;
        float4 w = *(const float4*)(W + i4);
        __align__(8) __half hv[4];
        hv[0] = __float2half_rn(w.x); hv[1] = __float2half_rn(w.y);
        hv[2] = __float2half_rn(w.z); hv[3] = __float2half_rn(w.w);
        *(uint2*)(g_wf + i4) = *(uint2*)hv;
        return;
    }

    __shared__ float tile[C_ * 33];
    __shared__ float red[8 * 32];
    __shared__ float rn[32];

    int b  = blockIdx.x >> 7;
    int n0 = (blockIdx.x & 127) * 32;
    int t  = threadIdx.x;
    int nl = t & 31;
    int cg = t >> 5;

    const float* xb = x + (size_t)b * C_ * N_;
#pragma unroll 8
    for (int p = 0; p < 32; ++p) {
        int c = cg + p * 8;
        tile[c * 33 + nl] = xb[(size_t)c * N_ + n0 + nl];
    }
    __syncthreads();

    float ss = 0.f;
#pragma unroll 8
    for (int c = cg; c < C_; c += 8) { float v = tile[c * 33 + nl]; ss += v * v; }
    red[cg * 32 + nl] = ss;
    __syncthreads();
    if (t < 32) {
        float s = 0.f;
#pragma unroll
        for (int g = 0; g < 8; ++g) s += red[g * 32 + t];
        rn[t] = 1.f / fmaxf(sqrtf(s), 1e-8f);
    }
    __syncthreads();

#pragma unroll 8
    for (int n = 0; n < 32; ++n) {
        size_t idx = (size_t)(b * N_ + n0 + n) * C_ + t;
        float xv = tile[t * 33 + n];
        g_xf[idx] = __float2half_rn(xv);
        g_qf[idx] = __float2half_rn(xv * rn[n]);
    }
}

// ---------------------------------------------------------------------------
// fused GEMM: blocks [0,TRI) = sim tile (triangular bx<=by, dual stmatrix
// epilogue + mirror); blocks [TRI,TRI+64) = conv tile (fp32 Ds epilogue).
// 128x128 tiles, 2 CTA/SM, 3-stage, 64x32 warp tiles (R10-proven mainloop).
// ---------------------------------------------------------------------------
__global__ void __launch_bounds__(256, 2) k_gemm(const float* __restrict__ bias) {
    extern __shared__ __align__(128) char sm[];
    const uint32_t smb = smem_u32(sm);
    const int t = threadIdx.x;
    const int b = blockIdx.z;

    const bool is_sim = (blockIdx.x < TRI);
    int bx, by;
    if (is_sim) {
        int id = blockIdx.x;
        int byy = (int)((sqrtf(8.f * id + 1.f) - 1.f) * 0.5f);
        while ((byy + 1) * (byy + 2) / 2 <= id) ++byy;
        while (byy * (byy + 1) / 2 > id) --byy;
        by = byy; bx = id - byy * (byy + 1) / 2;   // bx <= by
    } else {
        int id2 = blockIdx.x - TRI;
        bx = id2 & 31; by = id2 >> 5;              // conv: 32 x 2
    }

    constexpr int KCH = C_ / 32;

    const __half *af, *bf;
    if (is_sim) {
        af = g_qf + (size_t)b * N_ * C_ + (size_t)bx * 128 * C_;
        bf = g_qf + (size_t)b * N_ * C_ + (size_t)by * 128 * C_;
    } else {
        af = g_xf + (size_t)b * N_ * C_ + (size_t)bx * 128 * C_;
        bf = g_wf + (size_t)by * 128 * C_;
    }

    const int wid = t >> 5, lane = t & 31;
    const int wm = wid >> 2, wn = wid & 3;
    const int m0w = wm * 64, n0w = wn * 32;

    float acc[4][4][4];
#pragma unroll
    for (int i = 0; i < 4; ++i)
#pragma unroll
        for (int j = 0; j < 4; ++j)
#pragma unroll
            for (int r = 0; r < 4; ++r) acc[i][j][r] = 0.f;

#define PF1(kc_) do {                                                          \
        uint32_t st_ = smb + (uint32_t)((kc_) % 3) * 16384u;                   \
        int k0_ = (kc_) * 32;                                                  \
        _Pragma("unroll")                                                      \
        for (int i_ = 0; i_ < 2; ++i_) {                                       \
            int lin_ = t + i_ * 256;                                           \
            int row_ = lin_ >> 2, ch_ = lin_ & 3;                              \
            uint32_t so_ = swz(row_, ch_);                                     \
            CP16(st_ + so_,        af + (size_t)row_ * C_ + k0_ + ch_ * 8);    \
            CP16(st_ + 8192 + so_, bf + (size_t)row_ * C_ + k0_ + ch_ * 8);    \
        }                                                                      \
    } while (0)

    PF1(0); CPCOMMIT();
    PF1(1); CPCOMMIT();

    const int asub   = lane >> 3;
    const int arow   = (asub & 1) * 8 + (lane & 7);
    const int achoff = asub >> 1;
    const int bsub   = (lane >> 3) & 1;
    const int brow   = lane & 7;

#pragma unroll 1
    for (int kc = 0; kc < KCH; ++kc) {
        if (kc + 1 < KCH) CPWAIT1(); else CPWAIT0();
        __syncthreads();
        if (kc + 2 < KCH) { PF1(kc + 2); CPCOMMIT(); }

        uint32_t st = smb + (uint32_t)(kc % 3) * 16384u;
#pragma unroll
        for (int ks = 0; ks < 2; ++ks) {
            uint32_t Ah[4][4], Bh[4][2];
#pragma unroll
            for (int i = 0; i < 4; ++i)
                LDSM_X4(Ah[i], st + swz(m0w + i * 16 + arow, ks * 2 + achoff));
#pragma unroll
            for (int j = 0; j < 4; ++j)
                LDSM_X2(Bh[j], st + 8192 + swz(n0w + j * 8 + brow, ks * 2 + bsub));
#pragma unroll
            for (int i = 0; i < 4; ++i)
#pragma unroll
                for (int j = 0; j < 4; ++j)
                    MMAH(acc[i][j], Ah[i], Bh[j]);
        }
    }
#undef PF1

    if (is_sim) {
        // ---- sim epilogue: dual stmatrix staging, two half-passes ----
        __half* Ph = (__half*)sm;                 // 64 x 136 = 17408 B
        __half* Pt = (__half*)(sm + 17408);       // 128 x 72 = 18432 B
        const uint32_t ptb = smb + 17408;
        const int g  = lane >> 3;
        const int lr = lane & 7;

#pragma unroll 1
        for (int h = 0; h < 2; ++h) {
            __syncthreads();
            if (wm == h) {
#pragma unroll
                for (int i = 0; i < 4; ++i) {
#pragma unroll
                    for (int jp = 0; jp < 2; ++jp) {
                        uint32_t d0 = relu2h2(acc[i][2*jp][0],   acc[i][2*jp][1]);
                        uint32_t d1 = relu2h2(acc[i][2*jp][2],   acc[i][2*jp][3]);
                        uint32_t d2 = relu2h2(acc[i][2*jp+1][0], acc[i][2*jp+1][1]);
                        uint32_t d3 = relu2h2(acc[i][2*jp+1][2], acc[i][2*jp+1][3]);
                        int row = i * 16 + (g & 1) * 8 + lr;
                        int col = n0w + jp * 16 + (g >> 1) * 8;
                        STSM_X4(smb + (uint32_t)(row * 136 + col) * 2u, d0, d1, d2, d3);
                        int rowt = n0w + jp * 16 + (g >> 1) * 8 + lr;
                        int colt = i * 16 + (g & 1) * 8;
                        STSM_X4_T(ptb + (uint32_t)(rowt * 72 + colt) * 2u, d0, d1, d2, d3);
                    }
                }
            }
            __syncthreads();

            // direct (coalesced): P[bx*128 + h*64 + r][by*128 + 0..127]
            {
                const int r = t >> 2, q = t & 3;
                const uint4* src = (const uint4*)(Ph + r * 136) + q * 4;
                uint4* dst = (uint4*)(g_p + (size_t)b * N_ * N_
                                      + (size_t)(bx * 128 + h * 64 + r) * N_
                                      + by * 128) + q * 4;
#pragma unroll
                for (int u = 0; u < 4; ++u) dst[u] = src[u];
            }

            // mirror (coalesced, bx != by): P[by*128 + rt][bx*128 + h*64 + 0..63]
            if (bx != by) {
                const int rt = t >> 1, hc = t & 1;
                const uint4* src = (const uint4*)(Pt + rt * 72) + hc * 4;
                uint4* dst = (uint4*)(g_p + (size_t)b * N_ * N_
                                      + (size_t)(by * 128 + rt) * N_
                                      + bx * 128 + h * 64) + hc * 4;
#pragma unroll
                for (int u = 0; u < 4; ++u) dst[u] = src[u];
            }
        }
    } else {
        // ---- conv epilogue: fp32 Ds, two half-passes, fp16 store ----
        float* Ds = (float*)sm;     // 64 * 129 * 4 = 33024 B
        const int jj = t & 127, seg = t >> 7;
        float bv = bias[by * 128 + jj];

#pragma unroll 1
        for (int h = 0; h < 2; ++h) {
            __syncthreads();
            if (wm == h) {
#pragma unroll
                for (int i = 0; i < 4; ++i) {
                    int lr0 = i * 16 + (lane >> 2);
#pragma unroll
                    for (int j = 0; j < 4; ++j) {
                        int c0 = n0w + j * 8 + (lane & 3) * 2;
                        Ds[lr0 * 129 + c0]           = acc[i][j][0];
                        Ds[lr0 * 129 + c0 + 1]       = acc[i][j][1];
                        Ds[(lr0 + 8) * 129 + c0]     = acc[i][j][2];
                        Ds[(lr0 + 8) * 129 + c0 + 1] = acc[i][j][3];
                    }
                }
            }
            __syncthreads();

#pragma unroll 1
            for (int rb = 0; rb < 4; ++rb) {
                int lr0 = seg * 32 + rb * 8;
                __align__(16) __half hv[8];
#pragma unroll
                for (int u = 0; u < 8; ++u)
                    hv[u] = __float2half_rn(Ds[(lr0 + u) * 129 + jj] + bv);
                size_t off = (size_t)b * C_ * N_ + (size_t)(by * 128 + jj) * N_
                           + bx * 128 + h * 64 + lr0;
                *(uint4*)(g_v + off) = *(uint4*)hv;
            }
        }
    }
}

// ---------------------------------------------------------------------------
// k2: out GEMM. D[128n x 128c] = P[128,4096] * V[128c,4096]^T, fp32 out.
// 2 CTA/SM, 64x32 warp tiles, 5-stage cp.async.
// Grid (2 by, 32 bx, B): both c-halves of a P tile co-resident -> P read
// hits L2 the second time.
// ---------------------------------------------------------------------------
__global__ void __launch_bounds__(256, 2) k2(float* __restrict__ outf) {
    extern __shared__ __align__(128) char sm[];
    const uint32_t smb = smem_u32(sm);
    const int t = threadIdx.x;
    const int b = blockIdx.z;
    const int by = blockIdx.x, bx = blockIdx.y;   // by fastest -> P pair adjacent

    constexpr int KCH = N_ / 32;           // 128
    const __half* af = g_p + (size_t)b * N_ * N_ + (size_t)bx * 128 * N_;
    const __half* bf = g_v + (size_t)b * C_ * N_ + (size_t)by * 128 * N_;

    const int wid = t >> 5, lane = t & 31;
    const int wm = wid >> 2, wn = wid & 3;
    const int m0w = wm * 64, n0w = wn * 32;

    float acc[4][4][4];
#pragma unroll
    for (int i = 0; i < 4; ++i)
#pragma unroll
        for (int j = 0; j < 4; ++j)
#pragma unroll
            for (int r = 0; r < 4; ++r) acc[i][j][r] = 0.f;

#define PF2(kc_) do {                                                          \
        uint32_t st_ = smb + (uint32_t)((kc_) % 5) * 16384u;                   \
        int k0_ = (kc_) * 32;                                                  \
        _Pragma("unroll")                                                      \
        for (int i_ = 0; i_ < 2; ++i_) {                                       \
            int lin_ = t + i_ * 256;                                           \
            int row_ = lin_ >> 2, ch_ = lin_ & 3;                              \
            uint32_t so_ = swz(row_, ch_);                                     \
            CP16(st_ + so_,        af + (size_t)row_ * N_ + k0_ + ch_ * 8);    \
            CP16(st_ + 8192 + so_, bf + (size_t)row_ * N_ + k0_ + ch_ * 8);    \
        }                                                                      \
    } while (0)

    PF2(0); CPCOMMIT();
    PF2(1); CPCOMMIT();
    PF2(2); CPCOMMIT();
    PF2(3); CPCOMMIT();

    const int asub   = lane >> 3;
    const int arow   = (asub & 1) * 8 + (lane & 7);
    const int achoff = asub >> 1;
    const int bsub   = (lane >> 3) & 1;
    const int brow   = lane & 7;

#pragma unroll 1
    for (int kc = 0; kc < KCH; ++kc) {
        if (kc + 4 < KCH) CPWAIT3(); else CPWAIT0();
        __syncthreads();
        if (kc + 4 < KCH) { PF2(kc + 4); CPCOMMIT(); }

        uint32_t st = smb + (uint32_t)(kc % 5) * 16384u;
#pragma unroll
        for (int ks = 0; ks < 2; ++ks) {
            uint32_t Ah[4][4], Bh[4][2];
#pragma unroll
            for (int i = 0; i < 4; ++i)
                LDSM_X4(Ah[i], st + swz(m0w + i * 16 + arow, ks * 2 + achoff));
#pragma unroll
            for (int j = 0; j < 4; ++j)
                LDSM_X2(Bh[j], st + 8192 + swz(n0w + j * 8 + brow, ks * 2 + bsub));
#pragma unroll
            for (int i = 0; i < 4; ++i)
#pragma unroll
                for (int j = 0; j < 4; ++j)
                    MMAH(acc[i][j], Ah[i], Bh[j]);
        }
    }
#undef PF2

    float* Ds = (float*)sm;     // 64 * 129 * 4 = 33024 B
    const int jj = t & 127, seg = t >> 7;

#pragma unroll 1
    for (int h = 0; h < 2; ++h) {
        __syncthreads();
        if (wm == h) {
#pragma unroll
            for (int i = 0; i < 4; ++i) {
                int lr0 = i * 16 + (lane >> 2);
#pragma unroll
                for (int j = 0; j < 4; ++j) {
                    int c0 = n0w + j * 8 + (lane & 3) * 2;
                    Ds[lr0 * 129 + c0]           = acc[i][j][0];
                    Ds[lr0 * 129 + c0 + 1]       = acc[i][j][1];
                    Ds[(lr0 + 8) * 129 + c0]     = acc[i][j][2];
                    Ds[(lr0 + 8) * 129 + c0 + 1] = acc[i][j][3];
                }
            }
        }
        __syncthreads();

#pragma unroll 1
        for (int rb = 0; rb < 4; ++rb) {
            int lr0 = seg * 32 + rb * 8;
            float* orow = outf + (size_t)b * C_ * N_ + (size_t)(by * 128 + jj) * N_
                        + bx * 128 + h * 64 + lr0;
            float4 v0, v1;
            v0.x = Ds[(lr0 + 0) * 129 + jj];
            v0.y = Ds[(lr0 + 1) * 129 + jj];
            v0.z = Ds[(lr0 + 2) * 129 + jj];
            v0.w = Ds[(lr0 + 3) * 129 + jj];
            v1.x = Ds[(lr0 + 4) * 129 + jj];
            v1.y = Ds[(lr0 + 5) * 129 + jj];
            v1.z = Ds[(lr0 + 6) * 129 + jj];
            v1.w = Ds[(lr0 + 7) * 129 + jj];
            *(float4*)(orow)     = v0;
            *(float4*)(orow + 4) = v1;
        }
    }
}

// ---------------------------------------------------------------------------
extern "C" void kernel_launch(void* const* d_in, const int* in_sizes, int n_in,
                              void* d_out, int out_size) {
    const float* x    = (const float*)d_in[0];
    const float* Wm   = (const float*)d_in[1];
    const float* bias = (const float*)d_in[2];
    float* out = (float*)d_out;

    const int SMEM1 = 3 * 16384;   // 48KB, 2 CTA/SM (>= 35840 sim staging)
    const int SMEM2 = 5 * 16384;   // 80KB, 2 CTA/SM (160KB/SM <= 228KB)
    cudaFuncSetAttribute(k_gemm, cudaFuncAttributeMaxDynamicSharedMemorySize, SMEM1);
    cudaFuncSetAttribute(k2,     cudaFuncAttributeMaxDynamicSharedMemorySize, SMEM2);

    // fused prep: 512 norm blocks + 64 W-convert blocks
    k_prep<<<512 + 64, 256>>>(x, Wm);

    // fused GEMM: 528 sim tiles + 64 conv tiles, per batch
    k_gemm<<<dim3(TRI + 64, 1, B_), 256, SMEM1>>>(bias);

    // out GEMM: by fastest so both c-halves of each P tile are co-resident
    k2<<<dim3(C_ / 128, N_ / 128, B_), 256, SMEM2>>>(out);
}